// round 9
// baseline (speedup 1.0000x reference)
#include <cuda_runtime.h>
#include <cuda_fp16.h>
#include <math.h>

#define LAT 64
#define HID 256
#define NLAYERS 4
#define NBATCH 8192
#define SLOPEF 0.01f
#define TB 64
#define GB 32      // items per CTA in build kernel (8 groups x 4)
#define LUW 12     // warps (= items) per CTA in LU kernel
#define NITEMS (NLAYERS * NBATCH)

// Global scratch: masks, logdets, transposed W2, C = W2@W1, J staging
__device__ unsigned g_mask[NITEMS * (HID / 32)];
__device__ float g_logabs[NITEMS];
__device__ float g_W2t[NLAYERS * HID * LAT];   // [layer][h][d]
__device__ float g_C[NLAYERS * LAT * LAT];     // [layer][d][e]
// LU-friendly layout: g_J[item][c4][row*4 + comp]  (c4 = column chunk of 4)
__device__ float g_J[NITEMS * LAT * LAT];

// ---- f32x2 helpers (native on Blackwell incl. sm_100a) ----
__device__ __forceinline__ unsigned long long pack2(float a, float b) {
    unsigned long long r;
    asm("mov.b64 %0, {%1, %2};" : "=l"(r) : "f"(a), "f"(b));
    return r;
}
__device__ __forceinline__ unsigned long long fma2(unsigned long long a,
                                                   unsigned long long b,
                                                   unsigned long long c) {
    unsigned long long d;
    asm("fma.rn.f32x2 %0, %1, %2, %3;" : "=l"(d) : "l"(a), "l"(b), "l"(c));
    return d;
}
__device__ __forceinline__ void unpack2(unsigned long long p, float& lo, float& hi) {
    asm("mov.b64 {%0, %1}, %2;" : "=f"(lo), "=f"(hi) : "l"(p));
}

// ---------------------------------------------------------------------------
// Kernel 0: per-layer precompute: W2 transpose + C = W2 @ W1
// ---------------------------------------------------------------------------
__global__ void precomp_kernel(const float* __restrict__ W1,
                               const float* __restrict__ W2)
{
    extern __shared__ float ps[];          // W2s[64][257]
    float* W2s = ps;
    const int layer = blockIdx.x;
    const int t = threadIdx.x;
    const float* W1g = W1 + layer * HID * LAT;
    const float* W2g = W2 + layer * LAT * HID;

    for (int g = t; g < LAT * HID; g += 256) {
        int d = g >> 8, h = g & 255;
        W2s[d * 257 + h] = W2g[g];
    }
    __syncthreads();

    for (int g = t; g < HID * LAT; g += 256) {
        int h = g >> 6, d = g & 63;
        g_W2t[layer * HID * LAT + g] = W2s[d * 257 + h];
    }

    const int ty = t >> 4, tx = t & 15;
    const int d0 = ty * 4, e0 = tx * 4;
    float acc[4][4];
    #pragma unroll
    for (int i = 0; i < 4; i++)
        #pragma unroll
        for (int j = 0; j < 4; j++) acc[i][j] = 0.f;
    for (int h = 0; h < HID; h++) {
        float4 w1 = *(const float4*)&W1g[h * LAT + e0];
        #pragma unroll
        for (int i = 0; i < 4; i++) {
            float w2 = W2s[(d0 + i) * 257 + h];
            acc[i][0] += w2 * w1.x; acc[i][1] += w2 * w1.y;
            acc[i][2] += w2 * w1.z; acc[i][3] += w2 * w1.w;
        }
    }
    #pragma unroll
    for (int i = 0; i < 4; i++) {
        float4 v; v.x = acc[i][0]; v.y = acc[i][1]; v.z = acc[i][2]; v.w = acc[i][3];
        *(float4*)&g_C[layer * LAT * LAT + (d0 + i) * LAT + e0] = v;
    }
}

// ---------------------------------------------------------------------------
// Kernel 1: forward pass + post-layer mask bits
// ---------------------------------------------------------------------------
__device__ __forceinline__ void gemm_h_phase(
    const float* __restrict__ th, const float* __restrict__ W1t,
    const float* __restrict__ b1s, float* __restrict__ aS,
    int ty, int tx, bool leaky)
{
    for (int cb = 0; cb < 4; cb++) {
        const int c0 = cb * 64 + tx * 4;
        const int r0 = ty * 4;
        float acc[4][4];
        #pragma unroll
        for (int i = 0; i < 4; i++) {
            #pragma unroll
            for (int j = 0; j < 4; j++) acc[i][j] = b1s[c0 + j];
        }
        #pragma unroll 4
        for (int e = 0; e < LAT; e++) {
            float4 w = *(const float4*)&W1t[e * 260 + c0];
            #pragma unroll
            for (int i = 0; i < 4; i++) {
                float t = th[(r0 + i) * 68 + e];
                acc[i][0] += t * w.x;
                acc[i][1] += t * w.y;
                acc[i][2] += t * w.z;
                acc[i][3] += t * w.w;
            }
        }
        #pragma unroll
        for (int i = 0; i < 4; i++) {
            float4 v;
            if (leaky) {
                v.x = acc[i][0] > 0.f ? acc[i][0] : SLOPEF * acc[i][0];
                v.y = acc[i][1] > 0.f ? acc[i][1] : SLOPEF * acc[i][1];
                v.z = acc[i][2] > 0.f ? acc[i][2] : SLOPEF * acc[i][2];
                v.w = acc[i][3] > 0.f ? acc[i][3] : SLOPEF * acc[i][3];
            } else {
                v.x = acc[i][0]; v.y = acc[i][1]; v.z = acc[i][2]; v.w = acc[i][3];
            }
            *(float4*)&aS[(r0 + i) * 260 + c0] = v;
        }
    }
}

__global__ __launch_bounds__(256) void fwd_kernel(
    const float* __restrict__ z, const float* __restrict__ W1,
    const float* __restrict__ b1, const float* __restrict__ W2,
    const float* __restrict__ b2, float* __restrict__ out)
{
    extern __shared__ float s[];
    float* W1t = s;
    float* W2t = W1t + 64 * 260;
    float* aS  = W2t + 256 * 68;
    float* th  = aS + 64 * 260;
    float* b1s = th + 64 * 68;
    float* b2s = b1s + 256;

    const int tid = threadIdx.x;
    const int ty = tid >> 4, tx = tid & 15;
    const int b0 = blockIdx.x * TB;
    const int warp = tid >> 5, lane = tid & 31;

    for (int g = tid; g < TB * LAT; g += 256) {
        int r = g >> 6, e = g & 63;
        th[r * 68 + e] = z[(b0 + r) * LAT + e];
    }
    __syncthreads();

    for (int layer = 0; layer < NLAYERS; layer++) {
        const float* W1g = W1 + layer * HID * LAT;
        const float* W2g = W2 + layer * LAT * HID;
        for (int g = tid; g < HID * LAT; g += 256) {
            int h = g >> 6, e = g & 63;
            W1t[e * 260 + h] = W1g[g];
        }
        for (int g = tid; g < LAT * HID; g += 256) {
            int d = g >> 8, h = g & 255;
            W2t[h * 68 + d] = W2g[g];
        }
        for (int g = tid; g < HID; g += 256) b1s[g] = b1[layer * HID + g];
        if (tid < LAT) b2s[tid] = b2[layer * LAT + tid];
        __syncthreads();

        gemm_h_phase(th, W1t, b1s, aS, ty, tx, true);
        __syncthreads();

        {
            const int d0 = tx * 4, r0 = ty * 4;
            float acc[4][4];
            #pragma unroll
            for (int i = 0; i < 4; i++) {
                #pragma unroll
                for (int j = 0; j < 4; j++) acc[i][j] = b2s[d0 + j];
            }
            #pragma unroll 4
            for (int h = 0; h < HID; h++) {
                float4 w = *(const float4*)&W2t[h * 68 + d0];
                #pragma unroll
                for (int i = 0; i < 4; i++) {
                    float av = aS[(r0 + i) * 260 + h];
                    acc[i][0] += av * w.x;
                    acc[i][1] += av * w.y;
                    acc[i][2] += av * w.z;
                    acc[i][3] += av * w.w;
                }
            }
            #pragma unroll
            for (int i = 0; i < 4; i++) {
                float4 v; v.x = acc[i][0]; v.y = acc[i][1]; v.z = acc[i][2]; v.w = acc[i][3];
                *(float4*)&th[(r0 + i) * 68 + d0] = v;
            }
        }
        __syncthreads();

        gemm_h_phase(th, W1t, b1s, aS, ty, tx, false);
        __syncthreads();

        for (int sIdx = warp; sIdx < TB * 8; sIdx += 8) {
            int r = sIdx >> 3, wi = sIdx & 7;
            unsigned bits = __ballot_sync(0xffffffffu, aS[r * 260 + wi * 32 + lane] > 0.f);
            if (lane == 0) g_mask[(layer * NBATCH + b0 + r) * 8 + wi] = bits;
        }
        __syncthreads();
    }

    for (int g = tid; g < TB * LAT; g += 256) {
        int r = g >> 6, e = g & 63;
        out[(b0 + r) * LAT + e] = th[r * 68 + e];
    }
}

// ---------------------------------------------------------------------------
// Kernel 2a: sparse J build, 8x8 register tiles (64 threads per item),
// f32x2 FMAs, [c4][row] epilogue with C in smem. (unchanged from R8)
// ---------------------------------------------------------------------------
__global__ __launch_bounds__(512) void build_kernel(const float* __restrict__ W1)
{
    extern __shared__ float s[];
    float* W2c = s;                        // [256][64]: [h][d]
    float* W1r = W2c + HID * LAT;          // [256][64]: [h][e]
    float* Cs  = W1r + HID * LAT;          // [64][64]:  [d][e]
    unsigned short* sidx = (unsigned short*)(Cs + LAT * LAT);   // [GB][256]
    float* smisc = (float*)(sidx + GB * 256);
    int*   s_cnt  = (int*)smisc;           // GB
    float* s_csc  = smisc + GB;            // GB
    float* s_ssc  = smisc + 2 * GB;        // GB
    int*   s_wcnt  = (int*)(smisc + 3 * GB);    // [2][8]
    int*   s_wcnt2 = s_wcnt + 16;               // [2][8]

    const int layer = blockIdx.y;
    const int tid = threadIdx.x;
    const int team = tid >> 8;
    const int t = tid & 255;
    const int warp_t = t >> 5, lane = tid & 31;
    const int b_base = blockIdx.x * GB;

    {
        const float4* a = (const float4*)(g_W2t + layer * HID * LAT);
        const float4* b = (const float4*)(W1 + layer * HID * LAT);
        const float4* c = (const float4*)(g_C + layer * LAT * LAT);
        float4* da = (float4*)W2c;
        float4* db = (float4*)W1r;
        float4* dc = (float4*)Cs;
        for (int g = tid; g < HID * LAT / 4; g += 512) { da[g] = a[g]; db[g] = b[g]; }
        for (int g = tid; g < LAT * LAT / 4; g += 512) dc[g] = c[g];
    }

    for (int gl = 0; gl < 16; gl++) {
        int gg = team * 16 + gl;
        int b = b_base + gg;
        unsigned word = g_mask[(layer * NBATCH + b) * 8 + warp_t];
        int bit = (word >> lane) & 1;
        unsigned bal = __ballot_sync(0xffffffffu, bit);
        if (lane == 0) s_wcnt[team * 8 + warp_t] = __popc(bal);
        __syncthreads();
        int total = 0;
        #pragma unroll
        for (int w = 0; w < 8; w++) total += s_wcnt[team * 8 + w];
        int modeA = (total <= 128);
        int sel = modeA ? bit : 1 - bit;
        unsigned bs = __ballot_sync(0xffffffffu, sel);
        if (lane == 0) s_wcnt2[team * 8 + warp_t] = __popc(bs);
        __syncthreads();
        int base = 0;
        for (int w = 0; w < warp_t; w++) base += s_wcnt2[team * 8 + w];
        if (sel) sidx[gg * 256 + base + __popc(bs & ((1u << lane) - 1u))] = (unsigned short)t;
        if (t == 0) {
            s_cnt[gg] = modeA ? total : HID - total;
            s_csc[gg] = modeA ? 0.01f : 1.0f;
            s_ssc[gg] = modeA ? 0.99f : -0.99f;
        }
        __syncthreads();
    }

    const int group = tid >> 6;
    const int t6 = tid & 63;
    const int d0 = (t6 >> 3) * 8;
    const int e0 = (t6 & 7) * 8;

    for (int it = 0; it < GB / 8; it++) {
        const int gg = group * (GB / 8) + it;
        const int cnt = s_cnt[gg];
        const float csc = s_csc[gg], ssc = s_ssc[gg];
        const unsigned short* idx = sidx + gg * 256;

        unsigned long long acc[4][8];
        #pragma unroll
        for (int p = 0; p < 4; p++)
            #pragma unroll
            for (int j = 0; j < 8; j++) acc[p][j] = 0ull;

        for (int j = 0; j < cnt; j++) {
            const int h = idx[j];
            ulonglong2 w2a = *(const ulonglong2*)&W2c[h * 64 + d0];
            ulonglong2 w2b = *(const ulonglong2*)&W2c[h * 64 + d0 + 4];
            float4 w1a = *(const float4*)&W1r[h * 64 + e0];
            float4 w1b = *(const float4*)&W1r[h * 64 + e0 + 4];
            unsigned long long q0 = pack2(w1a.x, w1a.x), q1 = pack2(w1a.y, w1a.y);
            unsigned long long q2 = pack2(w1a.z, w1a.z), q3 = pack2(w1a.w, w1a.w);
            unsigned long long q4 = pack2(w1b.x, w1b.x), q5 = pack2(w1b.y, w1b.y);
            unsigned long long q6 = pack2(w1b.z, w1b.z), q7 = pack2(w1b.w, w1b.w);
            acc[0][0] = fma2(w2a.x, q0, acc[0][0]); acc[0][1] = fma2(w2a.x, q1, acc[0][1]);
            acc[0][2] = fma2(w2a.x, q2, acc[0][2]); acc[0][3] = fma2(w2a.x, q3, acc[0][3]);
            acc[0][4] = fma2(w2a.x, q4, acc[0][4]); acc[0][5] = fma2(w2a.x, q5, acc[0][5]);
            acc[0][6] = fma2(w2a.x, q6, acc[0][6]); acc[0][7] = fma2(w2a.x, q7, acc[0][7]);
            acc[1][0] = fma2(w2a.y, q0, acc[1][0]); acc[1][1] = fma2(w2a.y, q1, acc[1][1]);
            acc[1][2] = fma2(w2a.y, q2, acc[1][2]); acc[1][3] = fma2(w2a.y, q3, acc[1][3]);
            acc[1][4] = fma2(w2a.y, q4, acc[1][4]); acc[1][5] = fma2(w2a.y, q5, acc[1][5]);
            acc[1][6] = fma2(w2a.y, q6, acc[1][6]); acc[1][7] = fma2(w2a.y, q7, acc[1][7]);
            acc[2][0] = fma2(w2b.x, q0, acc[2][0]); acc[2][1] = fma2(w2b.x, q1, acc[2][1]);
            acc[2][2] = fma2(w2b.x, q2, acc[2][2]); acc[2][3] = fma2(w2b.x, q3, acc[2][3]);
            acc[2][4] = fma2(w2b.x, q4, acc[2][4]); acc[2][5] = fma2(w2b.x, q5, acc[2][5]);
            acc[2][6] = fma2(w2b.x, q6, acc[2][6]); acc[2][7] = fma2(w2b.x, q7, acc[2][7]);
            acc[3][0] = fma2(w2b.y, q0, acc[3][0]); acc[3][1] = fma2(w2b.y, q1, acc[3][1]);
            acc[3][2] = fma2(w2b.y, q2, acc[3][2]); acc[3][3] = fma2(w2b.y, q3, acc[3][3]);
            acc[3][4] = fma2(w2b.y, q4, acc[3][4]); acc[3][5] = fma2(w2b.y, q5, acc[3][5]);
            acc[3][6] = fma2(w2b.y, q6, acc[3][6]); acc[3][7] = fma2(w2b.y, q7, acc[3][7]);
        }

        const size_t itbase = (size_t)(layer * NBATCH + b_base + gg) * 4096;
        #pragma unroll
        for (int p = 0; p < 4; p++) {
            float lo[8], hi[8];
            #pragma unroll
            for (int j = 0; j < 8; j++) unpack2(acc[p][j], lo[j], hi[j]);
            const int rlo = d0 + 2 * p, rhi = rlo + 1;
            {
                float4 c0 = *(const float4*)&Cs[rlo * 64 + e0];
                float4 c1 = *(const float4*)&Cs[rlo * 64 + e0 + 4];
                float4 o0, o1;
                o0.x = csc * c0.x + ssc * lo[0]; o0.y = csc * c0.y + ssc * lo[1];
                o0.z = csc * c0.z + ssc * lo[2]; o0.w = csc * c0.w + ssc * lo[3];
                o1.x = csc * c1.x + ssc * lo[4]; o1.y = csc * c1.y + ssc * lo[5];
                o1.z = csc * c1.z + ssc * lo[6]; o1.w = csc * c1.w + ssc * lo[7];
                *(float4*)&g_J[itbase + (e0 >> 2) * 256 + rlo * 4] = o0;
                *(float4*)&g_J[itbase + ((e0 >> 2) + 1) * 256 + rlo * 4] = o1;
            }
            {
                float4 c0 = *(const float4*)&Cs[rhi * 64 + e0];
                float4 c1 = *(const float4*)&Cs[rhi * 64 + e0 + 4];
                float4 o0, o1;
                o0.x = csc * c0.x + ssc * hi[0]; o0.y = csc * c0.y + ssc * hi[1];
                o0.z = csc * c0.z + ssc * hi[2]; o0.w = csc * c0.w + ssc * hi[3];
                o1.x = csc * c1.x + ssc * hi[4]; o1.y = csc * c1.y + ssc * hi[5];
                o1.z = csc * c1.z + ssc * hi[6]; o1.w = csc * c1.w + ssc * hi[7];
                *(float4*)&g_J[itbase + (e0 >> 2) * 256 + rhi * 4] = o0;
                *(float4*)&g_J[itbase + ((e0 >> 2) + 1) * 256 + rhi * 4] = o1;
            }
        }
    }
}

// ---------------------------------------------------------------------------
// Kernel 2b: warp-per-item register LU, index pivoting, phased chunk trimming,
// ull2 rows + f32x2 update, exponent-accumulated log|det|.
// 384 threads (12 warps) per CTA. Lane owns rows lane, lane+32.
// ---------------------------------------------------------------------------
#define LU_PHASE(C0, KS, KE)                                                  \
    for (int k = (KS); k < (KE); k++) {                                       \
        unsigned k1 = act1 ? ((__float_as_uint(fabsf(a1)) & 0xFFFFFFC0u)      \
                              | (unsigned)r1i) : 0u;                          \
        unsigned k2 = act2 ? ((__float_as_uint(fabsf(a2)) & 0xFFFFFFC0u)      \
                              | (unsigned)r2i) : 0u;                          \
        unsigned key = k1 > k2 ? k1 : k2;                                     \
        _Pragma("unroll")                                                     \
        for (int off = 16; off; off >>= 1) {                                  \
            unsigned o = __shfl_xor_sync(0xffffffffu, key, off);              \
            key = o > key ? o : key;                                          \
        }                                                                     \
        const int pi = key & 63;                                              \
        const bool hi = (pi >= 32);                                           \
        const int pl = pi & 31;                                               \
        float cand = hi ? a2 : a1;                                            \
        float sv = __shfl_sync(0xffffffffu, cand, pl);                        \
        float pa = fabsf(sv);                                                 \
        unsigned pb = __float_as_uint(pa);                                    \
        esum += (int)(pb >> 23);                                              \
        mprod *= __uint_as_float((pb & 0x007FFFFFu) | 0x3F800000u);           \
        unsigned mb = __float_as_uint(mprod);                                 \
        esum += (int)(mb >> 23) - 127;                                        \
        mprod = __uint_as_float((mb & 0x007FFFFFu) | 0x3F800000u);            \
        float pinv = (pa > 1e-30f) ? __fdividef(1.0f, sv) : 0.f;              \
        if (pi == r1i) act1 = false;                                          \
        if (pi == r2i) act2 = false;                                          \
        float L1 = act1 ? a1 * pinv : 0.f;                                    \
        float L2 = act2 ? a2 * pinv : 0.f;                                    \
        unsigned long long nL1 = pack2(-L1, -L1);                             \
        unsigned long long nL2 = pack2(-L2, -L2);                             \
        const int chn = (k + 1) >> 2, compn = (k + 1) & 3;                    \
        _Pragma("unroll")                                                     \
        for (int c = (C0); c < 16; c++) {                                     \
            unsigned long long ux = hi ? A2[c].x : A1[c].x;                   \
            unsigned long long uy = hi ? A2[c].y : A1[c].y;                   \
            unsigned long long u0 = __shfl_sync(0xffffffffu, ux, pl);         \
            unsigned long long u1 = __shfl_sync(0xffffffffu, uy, pl);         \
            A1[c].x = fma2(u0, nL1, A1[c].x);                                 \
            A1[c].y = fma2(u1, nL1, A1[c].y);                                 \
            A2[c].x = fma2(u0, nL2, A2[c].x);                                 \
            A2[c].y = fma2(u1, nL2, A2[c].y);                                 \
            if (c == chn) {                                                   \
                float f0, f1, f2, f3;                                         \
                unpack2(A1[c].x, f0, f1); unpack2(A1[c].y, f2, f3);           \
                a1 = (compn == 0) ? f0 : (compn == 1) ? f1                    \
                   : (compn == 2) ? f2 : f3;                                  \
                unpack2(A2[c].x, f0, f1); unpack2(A2[c].y, f2, f3);           \
                a2 = (compn == 0) ? f0 : (compn == 1) ? f1                    \
                   : (compn == 2) ? f2 : f3;                                  \
            }                                                                 \
        }                                                                     \
    }

__global__ __launch_bounds__(LUW * 32) void lu_kernel(void)
{
    const int warp = threadIdx.x >> 5, lane = threadIdx.x & 31;
    const int item = blockIdx.x * LUW + warp;
    if (item >= NITEMS) return;

    const size_t base = (size_t)item * 4096;
    ulonglong2 A1[16], A2[16];
    #pragma unroll
    for (int c = 0; c < 16; c++) {
        A1[c] = *(const ulonglong2*)&g_J[base + c * 256 + lane * 4];
        A2[c] = *(const ulonglong2*)&g_J[base + c * 256 + (lane + 32) * 4];
    }

    const int r1i = lane, r2i = lane + 32;
    bool act1 = true, act2 = true;
    float a1, a2, dmy;
    unpack2(A1[0].x, a1, dmy);
    unpack2(A2[0].x, a2, dmy);
    float mprod = 1.f;
    int esum = 0;

    LU_PHASE(0,  0, 16)
    LU_PHASE(4, 16, 32)
    LU_PHASE(8, 32, 48)
    LU_PHASE(12, 48, 64)

    if (lane == 0) {
        float la = ((float)(esum - 64 * 127)) * 0.69314718055994531f
                 + __logf(mprod);
        g_logabs[item] = la;
    }
}

// ---------------------------------------------------------------------------
// Kernel 3: ldj = sum_layers logsumexp(logabs.astype(f16)) with f16 emulation
// ---------------------------------------------------------------------------
__global__ __launch_bounds__(1024) void reduce_kernel(float* __restrict__ out)
{
    __shared__ float red[1024];
    const int tid = threadIdx.x;
    float ldj = 0.f;
    for (int layer = 0; layer < NLAYERS; layer++) {
        const float* la = g_logabs + layer * NBATCH;
        float mx = -1e30f;
        for (int b = tid; b < NBATCH; b += 1024) {
            float v = __half2float(__float2half(la[b]));
            mx = fmaxf(mx, v);
        }
        red[tid] = mx; __syncthreads();
        for (int s2 = 512; s2; s2 >>= 1) {
            if (tid < s2) red[tid] = fmaxf(red[tid], red[tid + s2]);
            __syncthreads();
        }
        float gmx = red[0]; __syncthreads();
        __half maxh = __float2half(gmx);
        float sum = 0.f;
        for (int b = tid; b < NBATCH; b += 1024) {
            __half xh = __float2half(la[b]);
            __half d = __hsub(xh, maxh);
            float e = expf(__half2float(d));
            sum += __half2float(__float2half(e));
        }
        red[tid] = sum; __syncthreads();
        for (int s2 = 512; s2; s2 >>= 1) {
            if (tid < s2) red[tid] += red[tid + s2];
            __syncthreads();
        }
        float tot = red[0]; __syncthreads();
        __half resh = __hadd(maxh, __float2half(logf(tot)));
        ldj += __half2float(resh);
    }
    if (tid == 0) out[(size_t)NBATCH * LAT] = ldj;
}

// ---------------------------------------------------------------------------
extern "C" void kernel_launch(void* const* d_in, const int* in_sizes, int n_in,
                              void* d_out, int out_size)
{
    const float* z  = (const float*)d_in[0];
    const float* W1 = (const float*)d_in[1];
    const float* b1 = (const float*)d_in[2];
    const float* W2 = (const float*)d_in[3];
    const float* b2 = (const float*)d_in[4];
    float* out = (float*)d_out;

    const size_t SM0 = (size_t)(64 * 257) * sizeof(float);
    const size_t SM1 = (size_t)(64 * 260 + 256 * 68 + 64 * 260 + 64 * 68 + 256 + 64) * sizeof(float);
    const size_t SMB = (size_t)(HID * LAT * 2 + LAT * LAT) * sizeof(float)
                     + (size_t)(GB * 256) * sizeof(unsigned short)
                     + (size_t)(3 * GB + 32) * sizeof(float);

    cudaFuncSetAttribute(precomp_kernel, cudaFuncAttributeMaxDynamicSharedMemorySize, (int)SM0);
    cudaFuncSetAttribute(fwd_kernel, cudaFuncAttributeMaxDynamicSharedMemorySize, (int)SM1);
    cudaFuncSetAttribute(build_kernel, cudaFuncAttributeMaxDynamicSharedMemorySize, (int)SMB);

    precomp_kernel<<<NLAYERS, 256, SM0>>>(W1, W2);
    fwd_kernel<<<NBATCH / TB, 256, SM1>>>(z, W1, b1, W2, b2, out);
    dim3 gb(NBATCH / GB, NLAYERS);
    build_kernel<<<gb, 512, SMB>>>(W1);
    lu_kernel<<<(NITEMS + LUW - 1) / LUW, LUW * 32>>>();
    reduce_kernel<<<1, 1024>>>(out);
}

// round 10
// speedup vs baseline: 1.0439x; 1.0439x over previous
#include <cuda_runtime.h>
#include <cuda_fp16.h>
#include <math.h>

#define LAT 64
#define HID 256
#define NLAYERS 4
#define NBATCH 8192
#define SLOPEF 0.01f
#define TB 64
#define GB 32      // items per CTA in build kernel (8 groups x 4)
#define LUW 12     // warps (= items) per CTA in LU kernel
#define NITEMS (NLAYERS * NBATCH)

// Global scratch: masks, logdets, transposed W2, C = W2@W1, J staging
__device__ unsigned g_mask[NITEMS * (HID / 32)];
__device__ float g_logabs[NITEMS];
__device__ float g_W2t[NLAYERS * HID * LAT];   // [layer][h][d]
__device__ float g_C[NLAYERS * LAT * LAT];     // [layer][d][e]
// LU-friendly layout: g_J[item][c4][row*4 + comp]  (c4 = column chunk of 4)
__device__ float g_J[NITEMS * LAT * LAT];

// ---- f32x2 helpers (native on Blackwell incl. sm_100a) ----
__device__ __forceinline__ unsigned long long pack2(float a, float b) {
    unsigned long long r;
    asm("mov.b64 %0, {%1, %2};" : "=l"(r) : "f"(a), "f"(b));
    return r;
}
__device__ __forceinline__ unsigned long long fma2(unsigned long long a,
                                                   unsigned long long b,
                                                   unsigned long long c) {
    unsigned long long d;
    asm("fma.rn.f32x2 %0, %1, %2, %3;" : "=l"(d) : "l"(a), "l"(b), "l"(c));
    return d;
}
__device__ __forceinline__ void unpack2(unsigned long long p, float& lo, float& hi) {
    asm("mov.b64 {%0, %1}, %2;" : "=f"(lo), "=f"(hi) : "l"(p));
}

// ---------------------------------------------------------------------------
// Kernel 0: per-layer precompute: W2 transpose + C = W2 @ W1
// ---------------------------------------------------------------------------
__global__ void precomp_kernel(const float* __restrict__ W1,
                               const float* __restrict__ W2)
{
    extern __shared__ float ps[];          // W2s[64][257]
    float* W2s = ps;
    const int layer = blockIdx.x;
    const int t = threadIdx.x;
    const float* W1g = W1 + layer * HID * LAT;
    const float* W2g = W2 + layer * LAT * HID;

    for (int g = t; g < LAT * HID; g += 256) {
        int d = g >> 8, h = g & 255;
        W2s[d * 257 + h] = W2g[g];
    }
    __syncthreads();

    for (int g = t; g < HID * LAT; g += 256) {
        int h = g >> 6, d = g & 63;
        g_W2t[layer * HID * LAT + g] = W2s[d * 257 + h];
    }

    const int ty = t >> 4, tx = t & 15;
    const int d0 = ty * 4, e0 = tx * 4;
    float acc[4][4];
    #pragma unroll
    for (int i = 0; i < 4; i++)
        #pragma unroll
        for (int j = 0; j < 4; j++) acc[i][j] = 0.f;
    for (int h = 0; h < HID; h++) {
        float4 w1 = *(const float4*)&W1g[h * LAT + e0];
        #pragma unroll
        for (int i = 0; i < 4; i++) {
            float w2 = W2s[(d0 + i) * 257 + h];
            acc[i][0] += w2 * w1.x; acc[i][1] += w2 * w1.y;
            acc[i][2] += w2 * w1.z; acc[i][3] += w2 * w1.w;
        }
    }
    #pragma unroll
    for (int i = 0; i < 4; i++) {
        float4 v; v.x = acc[i][0]; v.y = acc[i][1]; v.z = acc[i][2]; v.w = acc[i][3];
        *(float4*)&g_C[layer * LAT * LAT + (d0 + i) * LAT + e0] = v;
    }
}

// ---------------------------------------------------------------------------
// Kernel 1: forward pass + post-layer mask bits
// ---------------------------------------------------------------------------
__device__ __forceinline__ void gemm_h_phase(
    const float* __restrict__ th, const float* __restrict__ W1t,
    const float* __restrict__ b1s, float* __restrict__ aS,
    int ty, int tx, bool leaky)
{
    for (int cb = 0; cb < 4; cb++) {
        const int c0 = cb * 64 + tx * 4;
        const int r0 = ty * 4;
        float acc[4][4];
        #pragma unroll
        for (int i = 0; i < 4; i++) {
            #pragma unroll
            for (int j = 0; j < 4; j++) acc[i][j] = b1s[c0 + j];
        }
        #pragma unroll 4
        for (int e = 0; e < LAT; e++) {
            float4 w = *(const float4*)&W1t[e * 260 + c0];
            #pragma unroll
            for (int i = 0; i < 4; i++) {
                float t = th[(r0 + i) * 68 + e];
                acc[i][0] += t * w.x;
                acc[i][1] += t * w.y;
                acc[i][2] += t * w.z;
                acc[i][3] += t * w.w;
            }
        }
        #pragma unroll
        for (int i = 0; i < 4; i++) {
            float4 v;
            if (leaky) {
                v.x = acc[i][0] > 0.f ? acc[i][0] : SLOPEF * acc[i][0];
                v.y = acc[i][1] > 0.f ? acc[i][1] : SLOPEF * acc[i][1];
                v.z = acc[i][2] > 0.f ? acc[i][2] : SLOPEF * acc[i][2];
                v.w = acc[i][3] > 0.f ? acc[i][3] : SLOPEF * acc[i][3];
            } else {
                v.x = acc[i][0]; v.y = acc[i][1]; v.z = acc[i][2]; v.w = acc[i][3];
            }
            *(float4*)&aS[(r0 + i) * 260 + c0] = v;
        }
    }
}

__global__ __launch_bounds__(256) void fwd_kernel(
    const float* __restrict__ z, const float* __restrict__ W1,
    const float* __restrict__ b1, const float* __restrict__ W2,
    const float* __restrict__ b2, float* __restrict__ out)
{
    extern __shared__ float s[];
    float* W1t = s;
    float* W2t = W1t + 64 * 260;
    float* aS  = W2t + 256 * 68;
    float* th  = aS + 64 * 260;
    float* b1s = th + 64 * 68;
    float* b2s = b1s + 256;

    const int tid = threadIdx.x;
    const int ty = tid >> 4, tx = tid & 15;
    const int b0 = blockIdx.x * TB;
    const int warp = tid >> 5, lane = tid & 31;

    for (int g = tid; g < TB * LAT; g += 256) {
        int r = g >> 6, e = g & 63;
        th[r * 68 + e] = z[(b0 + r) * LAT + e];
    }
    __syncthreads();

    for (int layer = 0; layer < NLAYERS; layer++) {
        const float* W1g = W1 + layer * HID * LAT;
        const float* W2g = W2 + layer * LAT * HID;
        for (int g = tid; g < HID * LAT; g += 256) {
            int h = g >> 6, e = g & 63;
            W1t[e * 260 + h] = W1g[g];
        }
        for (int g = tid; g < LAT * HID; g += 256) {
            int d = g >> 8, h = g & 255;
            W2t[h * 68 + d] = W2g[g];
        }
        for (int g = tid; g < HID; g += 256) b1s[g] = b1[layer * HID + g];
        if (tid < LAT) b2s[tid] = b2[layer * LAT + tid];
        __syncthreads();

        gemm_h_phase(th, W1t, b1s, aS, ty, tx, true);
        __syncthreads();

        {
            const int d0 = tx * 4, r0 = ty * 4;
            float acc[4][4];
            #pragma unroll
            for (int i = 0; i < 4; i++) {
                #pragma unroll
                for (int j = 0; j < 4; j++) acc[i][j] = b2s[d0 + j];
            }
            #pragma unroll 4
            for (int h = 0; h < HID; h++) {
                float4 w = *(const float4*)&W2t[h * 68 + d0];
                #pragma unroll
                for (int i = 0; i < 4; i++) {
                    float av = aS[(r0 + i) * 260 + h];
                    acc[i][0] += av * w.x;
                    acc[i][1] += av * w.y;
                    acc[i][2] += av * w.z;
                    acc[i][3] += av * w.w;
                }
            }
            #pragma unroll
            for (int i = 0; i < 4; i++) {
                float4 v; v.x = acc[i][0]; v.y = acc[i][1]; v.z = acc[i][2]; v.w = acc[i][3];
                *(float4*)&th[(r0 + i) * 68 + d0] = v;
            }
        }
        __syncthreads();

        gemm_h_phase(th, W1t, b1s, aS, ty, tx, false);
        __syncthreads();

        for (int sIdx = warp; sIdx < TB * 8; sIdx += 8) {
            int r = sIdx >> 3, wi = sIdx & 7;
            unsigned bits = __ballot_sync(0xffffffffu, aS[r * 260 + wi * 32 + lane] > 0.f);
            if (lane == 0) g_mask[(layer * NBATCH + b0 + r) * 8 + wi] = bits;
        }
        __syncthreads();
    }

    for (int g = tid; g < TB * LAT; g += 256) {
        int r = g >> 6, e = g & 63;
        out[(b0 + r) * LAT + e] = th[r * 68 + e];
    }
}

// ---------------------------------------------------------------------------
// Kernel 2a: sparse J build, 8x8 register tiles (64 threads per item),
// f32x2 FMAs, [c4][row] epilogue with C in smem. (unchanged from R8)
// ---------------------------------------------------------------------------
__global__ __launch_bounds__(512) void build_kernel(const float* __restrict__ W1)
{
    extern __shared__ float s[];
    float* W2c = s;                        // [256][64]: [h][d]
    float* W1r = W2c + HID * LAT;          // [256][64]: [h][e]
    float* Cs  = W1r + HID * LAT;          // [64][64]:  [d][e]
    unsigned short* sidx = (unsigned short*)(Cs + LAT * LAT);   // [GB][256]
    float* smisc = (float*)(sidx + GB * 256);
    int*   s_cnt  = (int*)smisc;           // GB
    float* s_csc  = smisc + GB;            // GB
    float* s_ssc  = smisc + 2 * GB;        // GB
    int*   s_wcnt  = (int*)(smisc + 3 * GB);    // [2][8]
    int*   s_wcnt2 = s_wcnt + 16;               // [2][8]

    const int layer = blockIdx.y;
    const int tid = threadIdx.x;
    const int team = tid >> 8;
    const int t = tid & 255;
    const int warp_t = t >> 5, lane = tid & 31;
    const int b_base = blockIdx.x * GB;

    {
        const float4* a = (const float4*)(g_W2t + layer * HID * LAT);
        const float4* b = (const float4*)(W1 + layer * HID * LAT);
        const float4* c = (const float4*)(g_C + layer * LAT * LAT);
        float4* da = (float4*)W2c;
        float4* db = (float4*)W1r;
        float4* dc = (float4*)Cs;
        for (int g = tid; g < HID * LAT / 4; g += 512) { da[g] = a[g]; db[g] = b[g]; }
        for (int g = tid; g < LAT * LAT / 4; g += 512) dc[g] = c[g];
    }

    for (int gl = 0; gl < 16; gl++) {
        int gg = team * 16 + gl;
        int b = b_base + gg;
        unsigned word = g_mask[(layer * NBATCH + b) * 8 + warp_t];
        int bit = (word >> lane) & 1;
        unsigned bal = __ballot_sync(0xffffffffu, bit);
        if (lane == 0) s_wcnt[team * 8 + warp_t] = __popc(bal);
        __syncthreads();
        int total = 0;
        #pragma unroll
        for (int w = 0; w < 8; w++) total += s_wcnt[team * 8 + w];
        int modeA = (total <= 128);
        int sel = modeA ? bit : 1 - bit;
        unsigned bs = __ballot_sync(0xffffffffu, sel);
        if (lane == 0) s_wcnt2[team * 8 + warp_t] = __popc(bs);
        __syncthreads();
        int base = 0;
        for (int w = 0; w < warp_t; w++) base += s_wcnt2[team * 8 + w];
        if (sel) sidx[gg * 256 + base + __popc(bs & ((1u << lane) - 1u))] = (unsigned short)t;
        if (t == 0) {
            s_cnt[gg] = modeA ? total : HID - total;
            s_csc[gg] = modeA ? 0.01f : 1.0f;
            s_ssc[gg] = modeA ? 0.99f : -0.99f;
        }
        __syncthreads();
    }

    const int group = tid >> 6;
    const int t6 = tid & 63;
    const int d0 = (t6 >> 3) * 8;
    const int e0 = (t6 & 7) * 8;

    for (int it = 0; it < GB / 8; it++) {
        const int gg = group * (GB / 8) + it;
        const int cnt = s_cnt[gg];
        const float csc = s_csc[gg], ssc = s_ssc[gg];
        const unsigned short* idx = sidx + gg * 256;

        unsigned long long acc[4][8];
        #pragma unroll
        for (int p = 0; p < 4; p++)
            #pragma unroll
            for (int j = 0; j < 8; j++) acc[p][j] = 0ull;

        for (int j = 0; j < cnt; j++) {
            const int h = idx[j];
            ulonglong2 w2a = *(const ulonglong2*)&W2c[h * 64 + d0];
            ulonglong2 w2b = *(const ulonglong2*)&W2c[h * 64 + d0 + 4];
            float4 w1a = *(const float4*)&W1r[h * 64 + e0];
            float4 w1b = *(const float4*)&W1r[h * 64 + e0 + 4];
            unsigned long long q0 = pack2(w1a.x, w1a.x), q1 = pack2(w1a.y, w1a.y);
            unsigned long long q2 = pack2(w1a.z, w1a.z), q3 = pack2(w1a.w, w1a.w);
            unsigned long long q4 = pack2(w1b.x, w1b.x), q5 = pack2(w1b.y, w1b.y);
            unsigned long long q6 = pack2(w1b.z, w1b.z), q7 = pack2(w1b.w, w1b.w);
            acc[0][0] = fma2(w2a.x, q0, acc[0][0]); acc[0][1] = fma2(w2a.x, q1, acc[0][1]);
            acc[0][2] = fma2(w2a.x, q2, acc[0][2]); acc[0][3] = fma2(w2a.x, q3, acc[0][3]);
            acc[0][4] = fma2(w2a.x, q4, acc[0][4]); acc[0][5] = fma2(w2a.x, q5, acc[0][5]);
            acc[0][6] = fma2(w2a.x, q6, acc[0][6]); acc[0][7] = fma2(w2a.x, q7, acc[0][7]);
            acc[1][0] = fma2(w2a.y, q0, acc[1][0]); acc[1][1] = fma2(w2a.y, q1, acc[1][1]);
            acc[1][2] = fma2(w2a.y, q2, acc[1][2]); acc[1][3] = fma2(w2a.y, q3, acc[1][3]);
            acc[1][4] = fma2(w2a.y, q4, acc[1][4]); acc[1][5] = fma2(w2a.y, q5, acc[1][5]);
            acc[1][6] = fma2(w2a.y, q6, acc[1][6]); acc[1][7] = fma2(w2a.y, q7, acc[1][7]);
            acc[2][0] = fma2(w2b.x, q0, acc[2][0]); acc[2][1] = fma2(w2b.x, q1, acc[2][1]);
            acc[2][2] = fma2(w2b.x, q2, acc[2][2]); acc[2][3] = fma2(w2b.x, q3, acc[2][3]);
            acc[2][4] = fma2(w2b.x, q4, acc[2][4]); acc[2][5] = fma2(w2b.x, q5, acc[2][5]);
            acc[2][6] = fma2(w2b.x, q6, acc[2][6]); acc[2][7] = fma2(w2b.x, q7, acc[2][7]);
            acc[3][0] = fma2(w2b.y, q0, acc[3][0]); acc[3][1] = fma2(w2b.y, q1, acc[3][1]);
            acc[3][2] = fma2(w2b.y, q2, acc[3][2]); acc[3][3] = fma2(w2b.y, q3, acc[3][3]);
            acc[3][4] = fma2(w2b.y, q4, acc[3][4]); acc[3][5] = fma2(w2b.y, q5, acc[3][5]);
            acc[3][6] = fma2(w2b.y, q6, acc[3][6]); acc[3][7] = fma2(w2b.y, q7, acc[3][7]);
        }

        const size_t itbase = (size_t)(layer * NBATCH + b_base + gg) * 4096;
        #pragma unroll
        for (int p = 0; p < 4; p++) {
            float lo[8], hi[8];
            #pragma unroll
            for (int j = 0; j < 8; j++) unpack2(acc[p][j], lo[j], hi[j]);
            const int rlo = d0 + 2 * p, rhi = rlo + 1;
            {
                float4 c0 = *(const float4*)&Cs[rlo * 64 + e0];
                float4 c1 = *(const float4*)&Cs[rlo * 64 + e0 + 4];
                float4 o0, o1;
                o0.x = csc * c0.x + ssc * lo[0]; o0.y = csc * c0.y + ssc * lo[1];
                o0.z = csc * c0.z + ssc * lo[2]; o0.w = csc * c0.w + ssc * lo[3];
                o1.x = csc * c1.x + ssc * lo[4]; o1.y = csc * c1.y + ssc * lo[5];
                o1.z = csc * c1.z + ssc * lo[6]; o1.w = csc * c1.w + ssc * lo[7];
                *(float4*)&g_J[itbase + (e0 >> 2) * 256 + rlo * 4] = o0;
                *(float4*)&g_J[itbase + ((e0 >> 2) + 1) * 256 + rlo * 4] = o1;
            }
            {
                float4 c0 = *(const float4*)&Cs[rhi * 64 + e0];
                float4 c1 = *(const float4*)&Cs[rhi * 64 + e0 + 4];
                float4 o0, o1;
                o0.x = csc * c0.x + ssc * hi[0]; o0.y = csc * c0.y + ssc * hi[1];
                o0.z = csc * c0.z + ssc * hi[2]; o0.w = csc * c0.w + ssc * hi[3];
                o1.x = csc * c1.x + ssc * hi[4]; o1.y = csc * c1.y + ssc * hi[5];
                o1.z = csc * c1.z + ssc * hi[6]; o1.w = csc * c1.w + ssc * hi[7];
                *(float4*)&g_J[itbase + (e0 >> 2) * 256 + rhi * 4] = o0;
                *(float4*)&g_J[itbase + ((e0 >> 2) + 1) * 256 + rhi * 4] = o1;
            }
        }
    }
}

// ---------------------------------------------------------------------------
// Kernel 2b: warp-per-item register LU (R8 structure), REDUX hardware argmax.
// 384 threads (12 warps) per CTA. Lane owns rows lane, lane+32.
// ---------------------------------------------------------------------------
#define LU_PHASE(C0, KS, KE)                                                  \
    for (int k = (KS); k < (KE); k++) {                                       \
        unsigned k1 = act1 ? ((__float_as_uint(fabsf(a1)) & 0xFFFFFFC0u)      \
                              | (unsigned)r1i) : 0u;                          \
        unsigned k2 = act2 ? ((__float_as_uint(fabsf(a2)) & 0xFFFFFFC0u)      \
                              | (unsigned)r2i) : 0u;                          \
        unsigned key = __reduce_max_sync(0xffffffffu, k1 > k2 ? k1 : k2);     \
        const int pi = key & 63;                                              \
        const bool hi = (pi >= 32);                                           \
        const int pl = pi & 31;                                               \
        float cand = hi ? a2 : a1;                                            \
        float sv = __shfl_sync(0xffffffffu, cand, pl);                        \
        float pa = fabsf(sv);                                                 \
        la += __logf(fmaxf(pa, 1e-38f));                                      \
        float pinv = (pa > 1e-30f) ? __fdividef(1.0f, sv) : 0.f;              \
        if (pi == r1i) act1 = false;                                          \
        if (pi == r2i) act2 = false;                                          \
        float L1 = act1 ? a1 * pinv : 0.f;                                    \
        float L2 = act2 ? a2 * pinv : 0.f;                                    \
        const int chn = (k + 1) >> 2, compn = (k + 1) & 3;                    \
        _Pragma("unroll")                                                     \
        for (int c = (C0); c < 16; c++) {                                     \
            float4 up = hi ? A2[c] : A1[c];                                   \
            float u0 = __shfl_sync(0xffffffffu, up.x, pl);                    \
            float u1 = __shfl_sync(0xffffffffu, up.y, pl);                    \
            float u2 = __shfl_sync(0xffffffffu, up.z, pl);                    \
            float u3 = __shfl_sync(0xffffffffu, up.w, pl);                    \
            A1[c].x -= L1 * u0; A1[c].y -= L1 * u1;                           \
            A1[c].z -= L1 * u2; A1[c].w -= L1 * u3;                           \
            A2[c].x -= L2 * u0; A2[c].y -= L2 * u1;                           \
            A2[c].z -= L2 * u2; A2[c].w -= L2 * u3;                           \
            if (c == chn) {                                                   \
                a1 = (compn == 0) ? A1[c].x : (compn == 1) ? A1[c].y          \
                   : (compn == 2) ? A1[c].z : A1[c].w;                        \
                a2 = (compn == 0) ? A2[c].x : (compn == 1) ? A2[c].y          \
                   : (compn == 2) ? A2[c].z : A2[c].w;                        \
            }                                                                 \
        }                                                                     \
    }

__global__ __launch_bounds__(LUW * 32) void lu_kernel(void)
{
    const int warp = threadIdx.x >> 5, lane = threadIdx.x & 31;
    const int item = blockIdx.x * LUW + warp;
    if (item >= NITEMS) return;

    const size_t base = (size_t)item * 4096;
    float4 A1[16], A2[16];
    #pragma unroll
    for (int c = 0; c < 16; c++) {
        A1[c] = *(const float4*)&g_J[base + c * 256 + lane * 4];
        A2[c] = *(const float4*)&g_J[base + c * 256 + (lane + 32) * 4];
    }

    const int r1i = lane, r2i = lane + 32;
    bool act1 = true, act2 = true;
    float a1 = A1[0].x, a2 = A2[0].x;
    float la = 0.f;

    LU_PHASE(0,  0, 16)
    LU_PHASE(4, 16, 32)
    LU_PHASE(8, 32, 48)
    LU_PHASE(12, 48, 64)

    if (lane == 0) g_logabs[item] = la;
}

// ---------------------------------------------------------------------------
// Kernel 3: ldj = sum_layers logsumexp(logabs.astype(f16)) with f16 emulation
// ---------------------------------------------------------------------------
__global__ __launch_bounds__(1024) void reduce_kernel(float* __restrict__ out)
{
    __shared__ float red[1024];
    const int tid = threadIdx.x;
    float ldj = 0.f;
    for (int layer = 0; layer < NLAYERS; layer++) {
        const float* la = g_logabs + layer * NBATCH;
        float mx = -1e30f;
        for (int b = tid; b < NBATCH; b += 1024) {
            float v = __half2float(__float2half(la[b]));
            mx = fmaxf(mx, v);
        }
        red[tid] = mx; __syncthreads();
        for (int s2 = 512; s2; s2 >>= 1) {
            if (tid < s2) red[tid] = fmaxf(red[tid], red[tid + s2]);
            __syncthreads();
        }
        float gmx = red[0]; __syncthreads();
        __half maxh = __float2half(gmx);
        float sum = 0.f;
        for (int b = tid; b < NBATCH; b += 1024) {
            __half xh = __float2half(la[b]);
            __half d = __hsub(xh, maxh);
            float e = expf(__half2float(d));
            sum += __half2float(__float2half(e));
        }
        red[tid] = sum; __syncthreads();
        for (int s2 = 512; s2; s2 >>= 1) {
            if (tid < s2) red[tid] += red[tid + s2];
            __syncthreads();
        }
        float tot = red[0]; __syncthreads();
        __half resh = __hadd(maxh, __float2half(logf(tot)));
        ldj += __half2float(resh);
    }
    if (tid == 0) out[(size_t)NBATCH * LAT] = ldj;
}

// ---------------------------------------------------------------------------
extern "C" void kernel_launch(void* const* d_in, const int* in_sizes, int n_in,
                              void* d_out, int out_size)
{
    const float* z  = (const float*)d_in[0];
    const float* W1 = (const float*)d_in[1];
    const float* b1 = (const float*)d_in[2];
    const float* W2 = (const float*)d_in[3];
    const float* b2 = (const float*)d_in[4];
    float* out = (float*)d_out;

    const size_t SM0 = (size_t)(64 * 257) * sizeof(float);
    const size_t SM1 = (size_t)(64 * 260 + 256 * 68 + 64 * 260 + 64 * 68 + 256 + 64) * sizeof(float);
    const size_t SMB = (size_t)(HID * LAT * 2 + LAT * LAT) * sizeof(float)
                     + (size_t)(GB * 256) * sizeof(unsigned short)
                     + (size_t)(3 * GB + 32) * sizeof(float);

    cudaFuncSetAttribute(precomp_kernel, cudaFuncAttributeMaxDynamicSharedMemorySize, (int)SM0);
    cudaFuncSetAttribute(fwd_kernel, cudaFuncAttributeMaxDynamicSharedMemorySize, (int)SM1);
    cudaFuncSetAttribute(build_kernel, cudaFuncAttributeMaxDynamicSharedMemorySize, (int)SMB);

    precomp_kernel<<<NLAYERS, 256, SM0>>>(W1, W2);
    fwd_kernel<<<NBATCH / TB, 256, SM1>>>(z, W1, b1, W2, b2, out);
    dim3 gb(NBATCH / GB, NLAYERS);
    build_kernel<<<gb, 512, SMB>>>(W1);
    lu_kernel<<<(NITEMS + LUW - 1) / LUW, LUW * 32>>>();
    reduce_kernel<<<1, 1024>>>(out);
}

// round 11
// speedup vs baseline: 1.0741x; 1.0289x over previous
#include <cuda_runtime.h>
#include <cuda_fp16.h>
#include <math.h>

#define LAT 64
#define HID 256
#define NLAYERS 4
#define NBATCH 8192
#define SLOPEF 0.01f
#define TB 64
#define GB 32      // items per CTA in build kernel (8 groups x 4)
#define LUW 12     // warps (= items) per CTA in LU kernel
#define NITEMS (NLAYERS * NBATCH)

// Global scratch: masks, logdets, transposed W2, C = W2@W1, J staging
__device__ unsigned g_mask[NITEMS * (HID / 32)];
__device__ float g_logabs[NITEMS];
__device__ float g_W2t[NLAYERS * HID * LAT];   // [layer][h][d]
__device__ float g_C[NLAYERS * LAT * LAT];     // [layer][d][e]
// LU-friendly layout: g_J[item][c4][row*4 + comp]  (c4 = column chunk of 4)
__device__ float g_J[NITEMS * LAT * LAT];

// ---- f32x2 helpers (native on Blackwell incl. sm_100a) ----
__device__ __forceinline__ unsigned long long pack2(float a, float b) {
    unsigned long long r;
    asm("mov.b64 %0, {%1, %2};" : "=l"(r) : "f"(a), "f"(b));
    return r;
}
__device__ __forceinline__ unsigned long long fma2(unsigned long long a,
                                                   unsigned long long b,
                                                   unsigned long long c) {
    unsigned long long d;
    asm("fma.rn.f32x2 %0, %1, %2, %3;" : "=l"(d) : "l"(a), "l"(b), "l"(c));
    return d;
}
__device__ __forceinline__ void unpack2(unsigned long long p, float& lo, float& hi) {
    asm("mov.b64 {%0, %1}, %2;" : "=f"(lo), "=f"(hi) : "l"(p));
}

// ---------------------------------------------------------------------------
// Kernel 0: per-layer precompute: W2 transpose + C = W2 @ W1
// ---------------------------------------------------------------------------
__global__ void precomp_kernel(const float* __restrict__ W1,
                               const float* __restrict__ W2)
{
    extern __shared__ float ps[];          // W2s[64][257]
    float* W2s = ps;
    const int layer = blockIdx.x;
    const int t = threadIdx.x;
    const float* W1g = W1 + layer * HID * LAT;
    const float* W2g = W2 + layer * LAT * HID;

    for (int g = t; g < LAT * HID; g += 256) {
        int d = g >> 8, h = g & 255;
        W2s[d * 257 + h] = W2g[g];
    }
    __syncthreads();

    for (int g = t; g < HID * LAT; g += 256) {
        int h = g >> 6, d = g & 63;
        g_W2t[layer * HID * LAT + g] = W2s[d * 257 + h];
    }

    const int ty = t >> 4, tx = t & 15;
    const int d0 = ty * 4, e0 = tx * 4;
    float acc[4][4];
    #pragma unroll
    for (int i = 0; i < 4; i++)
        #pragma unroll
        for (int j = 0; j < 4; j++) acc[i][j] = 0.f;
    for (int h = 0; h < HID; h++) {
        float4 w1 = *(const float4*)&W1g[h * LAT + e0];
        #pragma unroll
        for (int i = 0; i < 4; i++) {
            float w2 = W2s[(d0 + i) * 257 + h];
            acc[i][0] += w2 * w1.x; acc[i][1] += w2 * w1.y;
            acc[i][2] += w2 * w1.z; acc[i][3] += w2 * w1.w;
        }
    }
    #pragma unroll
    for (int i = 0; i < 4; i++) {
        float4 v; v.x = acc[i][0]; v.y = acc[i][1]; v.z = acc[i][2]; v.w = acc[i][3];
        *(float4*)&g_C[layer * LAT * LAT + (d0 + i) * LAT + e0] = v;
    }
}

// ---------------------------------------------------------------------------
// Kernel 1: forward pass + post-layer mask bits
// ---------------------------------------------------------------------------
__device__ __forceinline__ void gemm_h_phase(
    const float* __restrict__ th, const float* __restrict__ W1t,
    const float* __restrict__ b1s, float* __restrict__ aS,
    int ty, int tx, bool leaky)
{
    for (int cb = 0; cb < 4; cb++) {
        const int c0 = cb * 64 + tx * 4;
        const int r0 = ty * 4;
        float acc[4][4];
        #pragma unroll
        for (int i = 0; i < 4; i++) {
            #pragma unroll
            for (int j = 0; j < 4; j++) acc[i][j] = b1s[c0 + j];
        }
        #pragma unroll 4
        for (int e = 0; e < LAT; e++) {
            float4 w = *(const float4*)&W1t[e * 260 + c0];
            #pragma unroll
            for (int i = 0; i < 4; i++) {
                float t = th[(r0 + i) * 68 + e];
                acc[i][0] += t * w.x;
                acc[i][1] += t * w.y;
                acc[i][2] += t * w.z;
                acc[i][3] += t * w.w;
            }
        }
        #pragma unroll
        for (int i = 0; i < 4; i++) {
            float4 v;
            if (leaky) {
                v.x = acc[i][0] > 0.f ? acc[i][0] : SLOPEF * acc[i][0];
                v.y = acc[i][1] > 0.f ? acc[i][1] : SLOPEF * acc[i][1];
                v.z = acc[i][2] > 0.f ? acc[i][2] : SLOPEF * acc[i][2];
                v.w = acc[i][3] > 0.f ? acc[i][3] : SLOPEF * acc[i][3];
            } else {
                v.x = acc[i][0]; v.y = acc[i][1]; v.z = acc[i][2]; v.w = acc[i][3];
            }
            *(float4*)&aS[(r0 + i) * 260 + c0] = v;
        }
    }
}

__global__ __launch_bounds__(256) void fwd_kernel(
    const float* __restrict__ z, const float* __restrict__ W1,
    const float* __restrict__ b1, const float* __restrict__ W2,
    const float* __restrict__ b2, float* __restrict__ out)
{
    extern __shared__ float s[];
    float* W1t = s;
    float* W2t = W1t + 64 * 260;
    float* aS  = W2t + 256 * 68;
    float* th  = aS + 64 * 260;
    float* b1s = th + 64 * 68;
    float* b2s = b1s + 256;

    const int tid = threadIdx.x;
    const int ty = tid >> 4, tx = tid & 15;
    const int b0 = blockIdx.x * TB;
    const int warp = tid >> 5, lane = tid & 31;

    for (int g = tid; g < TB * LAT; g += 256) {
        int r = g >> 6, e = g & 63;
        th[r * 68 + e] = z[(b0 + r) * LAT + e];
    }
    __syncthreads();

    for (int layer = 0; layer < NLAYERS; layer++) {
        const float* W1g = W1 + layer * HID * LAT;
        const float* W2g = W2 + layer * LAT * HID;
        for (int g = tid; g < HID * LAT; g += 256) {
            int h = g >> 6, e = g & 63;
            W1t[e * 260 + h] = W1g[g];
        }
        for (int g = tid; g < LAT * HID; g += 256) {
            int d = g >> 8, h = g & 255;
            W2t[h * 68 + d] = W2g[g];
        }
        for (int g = tid; g < HID; g += 256) b1s[g] = b1[layer * HID + g];
        if (tid < LAT) b2s[tid] = b2[layer * LAT + tid];
        __syncthreads();

        gemm_h_phase(th, W1t, b1s, aS, ty, tx, true);
        __syncthreads();

        {
            const int d0 = tx * 4, r0 = ty * 4;
            float acc[4][4];
            #pragma unroll
            for (int i = 0; i < 4; i++) {
                #pragma unroll
                for (int j = 0; j < 4; j++) acc[i][j] = b2s[d0 + j];
            }
            #pragma unroll 4
            for (int h = 0; h < HID; h++) {
                float4 w = *(const float4*)&W2t[h * 68 + d0];
                #pragma unroll
                for (int i = 0; i < 4; i++) {
                    float av = aS[(r0 + i) * 260 + h];
                    acc[i][0] += av * w.x;
                    acc[i][1] += av * w.y;
                    acc[i][2] += av * w.z;
                    acc[i][3] += av * w.w;
                }
            }
            #pragma unroll
            for (int i = 0; i < 4; i++) {
                float4 v; v.x = acc[i][0]; v.y = acc[i][1]; v.z = acc[i][2]; v.w = acc[i][3];
                *(float4*)&th[(r0 + i) * 68 + d0] = v;
            }
        }
        __syncthreads();

        gemm_h_phase(th, W1t, b1s, aS, ty, tx, false);
        __syncthreads();

        for (int sIdx = warp; sIdx < TB * 8; sIdx += 8) {
            int r = sIdx >> 3, wi = sIdx & 7;
            unsigned bits = __ballot_sync(0xffffffffu, aS[r * 260 + wi * 32 + lane] > 0.f);
            if (lane == 0) g_mask[(layer * NBATCH + b0 + r) * 8 + wi] = bits;
        }
        __syncthreads();
    }

    for (int g = tid; g < TB * LAT; g += 256) {
        int r = g >> 6, e = g & 63;
        out[(b0 + r) * LAT + e] = th[r * 68 + e];
    }
}

// ---------------------------------------------------------------------------
// Kernel 2a: sparse J build, 8x8 register tiles, f32x2 FMAs,
// software-pipelined unroll-2 inner loop (ushort2 index loads).
// ---------------------------------------------------------------------------
#define FMA_BLOCK(w2x, w2y, w2z, w2w, w1A, w1B)                                \
    {                                                                          \
        unsigned long long q0 = pack2(w1A.x, w1A.x), q1 = pack2(w1A.y, w1A.y); \
        unsigned long long q2 = pack2(w1A.z, w1A.z), q3 = pack2(w1A.w, w1A.w); \
        unsigned long long q4 = pack2(w1B.x, w1B.x), q5 = pack2(w1B.y, w1B.y); \
        unsigned long long q6 = pack2(w1B.z, w1B.z), q7 = pack2(w1B.w, w1B.w); \
        acc[0][0] = fma2(w2x, q0, acc[0][0]); acc[0][1] = fma2(w2x, q1, acc[0][1]); \
        acc[0][2] = fma2(w2x, q2, acc[0][2]); acc[0][3] = fma2(w2x, q3, acc[0][3]); \
        acc[0][4] = fma2(w2x, q4, acc[0][4]); acc[0][5] = fma2(w2x, q5, acc[0][5]); \
        acc[0][6] = fma2(w2x, q6, acc[0][6]); acc[0][7] = fma2(w2x, q7, acc[0][7]); \
        acc[1][0] = fma2(w2y, q0, acc[1][0]); acc[1][1] = fma2(w2y, q1, acc[1][1]); \
        acc[1][2] = fma2(w2y, q2, acc[1][2]); acc[1][3] = fma2(w2y, q3, acc[1][3]); \
        acc[1][4] = fma2(w2y, q4, acc[1][4]); acc[1][5] = fma2(w2y, q5, acc[1][5]); \
        acc[1][6] = fma2(w2y, q6, acc[1][6]); acc[1][7] = fma2(w2y, q7, acc[1][7]); \
        acc[2][0] = fma2(w2z, q0, acc[2][0]); acc[2][1] = fma2(w2z, q1, acc[2][1]); \
        acc[2][2] = fma2(w2z, q2, acc[2][2]); acc[2][3] = fma2(w2z, q3, acc[2][3]); \
        acc[2][4] = fma2(w2z, q4, acc[2][4]); acc[2][5] = fma2(w2z, q5, acc[2][5]); \
        acc[2][6] = fma2(w2z, q6, acc[2][6]); acc[2][7] = fma2(w2z, q7, acc[2][7]); \
        acc[3][0] = fma2(w2w, q0, acc[3][0]); acc[3][1] = fma2(w2w, q1, acc[3][1]); \
        acc[3][2] = fma2(w2w, q2, acc[3][2]); acc[3][3] = fma2(w2w, q3, acc[3][3]); \
        acc[3][4] = fma2(w2w, q4, acc[3][4]); acc[3][5] = fma2(w2w, q5, acc[3][5]); \
        acc[3][6] = fma2(w2w, q6, acc[3][6]); acc[3][7] = fma2(w2w, q7, acc[3][7]); \
    }

__global__ __launch_bounds__(512) void build_kernel(const float* __restrict__ W1)
{
    extern __shared__ float s[];
    float* W2c = s;                        // [256][64]: [h][d]
    float* W1r = W2c + HID * LAT;          // [256][64]: [h][e]
    float* Cs  = W1r + HID * LAT;          // [64][64]:  [d][e]
    unsigned short* sidx = (unsigned short*)(Cs + LAT * LAT);   // [GB][256]
    float* smisc = (float*)(sidx + GB * 256);
    int*   s_cnt  = (int*)smisc;           // GB
    float* s_csc  = smisc + GB;            // GB
    float* s_ssc  = smisc + 2 * GB;        // GB
    int*   s_wcnt  = (int*)(smisc + 3 * GB);    // [2][8]
    int*   s_wcnt2 = s_wcnt + 16;               // [2][8]

    const int layer = blockIdx.y;
    const int tid = threadIdx.x;
    const int team = tid >> 8;
    const int t = tid & 255;
    const int warp_t = t >> 5, lane = tid & 31;
    const int b_base = blockIdx.x * GB;

    {
        const float4* a = (const float4*)(g_W2t + layer * HID * LAT);
        const float4* b = (const float4*)(W1 + layer * HID * LAT);
        const float4* c = (const float4*)(g_C + layer * LAT * LAT);
        float4* da = (float4*)W2c;
        float4* db = (float4*)W1r;
        float4* dc = (float4*)Cs;
        for (int g = tid; g < HID * LAT / 4; g += 512) { da[g] = a[g]; db[g] = b[g]; }
        for (int g = tid; g < LAT * LAT / 4; g += 512) dc[g] = c[g];
    }

    for (int gl = 0; gl < 16; gl++) {
        int gg = team * 16 + gl;
        int b = b_base + gg;
        unsigned word = g_mask[(layer * NBATCH + b) * 8 + warp_t];
        int bit = (word >> lane) & 1;
        unsigned bal = __ballot_sync(0xffffffffu, bit);
        if (lane == 0) s_wcnt[team * 8 + warp_t] = __popc(bal);
        __syncthreads();
        int total = 0;
        #pragma unroll
        for (int w = 0; w < 8; w++) total += s_wcnt[team * 8 + w];
        int modeA = (total <= 128);
        int sel = modeA ? bit : 1 - bit;
        unsigned bs = __ballot_sync(0xffffffffu, sel);
        if (lane == 0) s_wcnt2[team * 8 + warp_t] = __popc(bs);
        __syncthreads();
        int base = 0;
        for (int w = 0; w < warp_t; w++) base += s_wcnt2[team * 8 + w];
        if (sel) sidx[gg * 256 + base + __popc(bs & ((1u << lane) - 1u))] = (unsigned short)t;
        if (t == 0) {
            s_cnt[gg] = modeA ? total : HID - total;
            s_csc[gg] = modeA ? 0.01f : 1.0f;
            s_ssc[gg] = modeA ? 0.99f : -0.99f;
        }
        __syncthreads();
    }

    const int group = tid >> 6;
    const int t6 = tid & 63;
    const int d0 = (t6 >> 3) * 8;
    const int e0 = (t6 & 7) * 8;

    for (int it = 0; it < GB / 8; it++) {
        const int gg = group * (GB / 8) + it;
        const int cnt = s_cnt[gg];
        const float csc = s_csc[gg], ssc = s_ssc[gg];
        const unsigned short* idx = sidx + gg * 256;

        unsigned long long acc[4][8];
        #pragma unroll
        for (int p = 0; p < 4; p++)
            #pragma unroll
            for (int j = 0; j < 8; j++) acc[p][j] = 0ull;

        int j = 0;
        for (; j + 2 <= cnt; j += 2) {
            // one 32-bit index load for both iterations; issue ALL operand
            // loads up-front so b's LDS latency hides under a's fma2 stream
            ushort2 hp = *(const ushort2*)&idx[j];
            const int ha = hp.x, hb = hp.y;
            ulonglong2 w2a0 = *(const ulonglong2*)&W2c[ha * 64 + d0];
            ulonglong2 w2a1 = *(const ulonglong2*)&W2c[ha * 64 + d0 + 4];
            float4 w1a0 = *(const float4*)&W1r[ha * 64 + e0];
            float4 w1a1 = *(const float4*)&W1r[ha * 64 + e0 + 4];
            ulonglong2 w2b0 = *(const ulonglong2*)&W2c[hb * 64 + d0];
            ulonglong2 w2b1 = *(const ulonglong2*)&W2c[hb * 64 + d0 + 4];
            float4 w1b0 = *(const float4*)&W1r[hb * 64 + e0];
            float4 w1b1 = *(const float4*)&W1r[hb * 64 + e0 + 4];
            FMA_BLOCK(w2a0.x, w2a0.y, w2a1.x, w2a1.y, w1a0, w1a1)
            FMA_BLOCK(w2b0.x, w2b0.y, w2b1.x, w2b1.y, w1b0, w1b1)
        }
        if (j < cnt) {
            const int ha = idx[j];
            ulonglong2 w2a0 = *(const ulonglong2*)&W2c[ha * 64 + d0];
            ulonglong2 w2a1 = *(const ulonglong2*)&W2c[ha * 64 + d0 + 4];
            float4 w1a0 = *(const float4*)&W1r[ha * 64 + e0];
            float4 w1a1 = *(const float4*)&W1r[ha * 64 + e0 + 4];
            FMA_BLOCK(w2a0.x, w2a0.y, w2a1.x, w2a1.y, w1a0, w1a1)
        }

        const size_t itbase = (size_t)(layer * NBATCH + b_base + gg) * 4096;
        #pragma unroll
        for (int p = 0; p < 4; p++) {
            float lo[8], hi[8];
            #pragma unroll
            for (int jj = 0; jj < 8; jj++) unpack2(acc[p][jj], lo[jj], hi[jj]);
            const int rlo = d0 + 2 * p, rhi = rlo + 1;
            {
                float4 c0 = *(const float4*)&Cs[rlo * 64 + e0];
                float4 c1 = *(const float4*)&Cs[rlo * 64 + e0 + 4];
                float4 o0, o1;
                o0.x = csc * c0.x + ssc * lo[0]; o0.y = csc * c0.y + ssc * lo[1];
                o0.z = csc * c0.z + ssc * lo[2]; o0.w = csc * c0.w + ssc * lo[3];
                o1.x = csc * c1.x + ssc * lo[4]; o1.y = csc * c1.y + ssc * lo[5];
                o1.z = csc * c1.z + ssc * lo[6]; o1.w = csc * c1.w + ssc * lo[7];
                *(float4*)&g_J[itbase + (e0 >> 2) * 256 + rlo * 4] = o0;
                *(float4*)&g_J[itbase + ((e0 >> 2) + 1) * 256 + rlo * 4] = o1;
            }
            {
                float4 c0 = *(const float4*)&Cs[rhi * 64 + e0];
                float4 c1 = *(const float4*)&Cs[rhi * 64 + e0 + 4];
                float4 o0, o1;
                o0.x = csc * c0.x + ssc * hi[0]; o0.y = csc * c0.y + ssc * hi[1];
                o0.z = csc * c0.z + ssc * hi[2]; o0.w = csc * c0.w + ssc * hi[3];
                o1.x = csc * c1.x + ssc * hi[4]; o1.y = csc * c1.y + ssc * hi[5];
                o1.z = csc * c1.z + ssc * hi[6]; o1.w = csc * c1.w + ssc * hi[7];
                *(float4*)&g_J[itbase + (e0 >> 2) * 256 + rhi * 4] = o0;
                *(float4*)&g_J[itbase + ((e0 >> 2) + 1) * 256 + rhi * 4] = o1;
            }
        }
    }
}

// ---------------------------------------------------------------------------
// Kernel 2b: warp-per-item register LU, REDUX argmax, 8-wide phase trimming.
// 384 threads (12 warps) per CTA. Lane owns rows lane, lane+32.
// ---------------------------------------------------------------------------
#define LU_PHASE(C0, KS, KE)                                                  \
    for (int k = (KS); k < (KE); k++) {                                       \
        unsigned k1 = act1 ? ((__float_as_uint(fabsf(a1)) & 0xFFFFFFC0u)      \
                              | (unsigned)r1i) : 0u;                          \
        unsigned k2 = act2 ? ((__float_as_uint(fabsf(a2)) & 0xFFFFFFC0u)      \
                              | (unsigned)r2i) : 0u;                          \
        unsigned key = __reduce_max_sync(0xffffffffu, k1 > k2 ? k1 : k2);     \
        const int pi = key & 63;                                              \
        const bool hi = (pi >= 32);                                           \
        const int pl = pi & 31;                                               \
        float cand = hi ? a2 : a1;                                            \
        float sv = __shfl_sync(0xffffffffu, cand, pl);                        \
        float pa = fabsf(sv);                                                 \
        la += __logf(fmaxf(pa, 1e-38f));                                      \
        float pinv = (pa > 1e-30f) ? __fdividef(1.0f, sv) : 0.f;              \
        if (pi == r1i) act1 = false;                                          \
        if (pi == r2i) act2 = false;                                          \
        float L1 = act1 ? a1 * pinv : 0.f;                                    \
        float L2 = act2 ? a2 * pinv : 0.f;                                    \
        const int chn = (k + 1) >> 2, compn = (k + 1) & 3;                    \
        _Pragma("unroll")                                                     \
        for (int c = (C0); c < 16; c++) {                                     \
            float4 up = hi ? A2[c] : A1[c];                                   \
            float u0 = __shfl_sync(0xffffffffu, up.x, pl);                    \
            float u1 = __shfl_sync(0xffffffffu, up.y, pl);                    \
            float u2 = __shfl_sync(0xffffffffu, up.z, pl);                    \
            float u3 = __shfl_sync(0xffffffffu, up.w, pl);                    \
            A1[c].x -= L1 * u0; A1[c].y -= L1 * u1;                           \
            A1[c].z -= L1 * u2; A1[c].w -= L1 * u3;                           \
            A2[c].x -= L2 * u0; A2[c].y -= L2 * u1;                           \
            A2[c].z -= L2 * u2; A2[c].w -= L2 * u3;                           \
            if (c == chn) {                                                   \
                a1 = (compn == 0) ? A1[c].x : (compn == 1) ? A1[c].y          \
                   : (compn == 2) ? A1[c].z : A1[c].w;                        \
                a2 = (compn == 0) ? A2[c].x : (compn == 1) ? A2[c].y          \
                   : (compn == 2) ? A2[c].z : A2[c].w;                        \
            }                                                                 \
        }                                                                     \
    }

__global__ __launch_bounds__(LUW * 32) void lu_kernel(void)
{
    const int warp = threadIdx.x >> 5, lane = threadIdx.x & 31;
    const int item = blockIdx.x * LUW + warp;
    if (item >= NITEMS) return;

    const size_t base = (size_t)item * 4096;
    float4 A1[16], A2[16];
    #pragma unroll
    for (int c = 0; c < 16; c++) {
        A1[c] = *(const float4*)&g_J[base + c * 256 + lane * 4];
        A2[c] = *(const float4*)&g_J[base + c * 256 + (lane + 32) * 4];
    }

    const int r1i = lane, r2i = lane + 32;
    bool act1 = true, act2 = true;
    float a1 = A1[0].x, a2 = A2[0].x;
    float la = 0.f;

    LU_PHASE(0,   0,  8)
    LU_PHASE(2,   8, 16)
    LU_PHASE(4,  16, 24)
    LU_PHASE(6,  24, 32)
    LU_PHASE(8,  32, 40)
    LU_PHASE(10, 40, 48)
    LU_PHASE(12, 48, 56)
    LU_PHASE(14, 56, 64)

    if (lane == 0) g_logabs[item] = la;
}

// ---------------------------------------------------------------------------
// Kernel 3: ldj = sum_layers logsumexp(logabs.astype(f16)) with f16 emulation
// ---------------------------------------------------------------------------
__global__ __launch_bounds__(1024) void reduce_kernel(float* __restrict__ out)
{
    __shared__ float red[1024];
    const int tid = threadIdx.x;
    float ldj = 0.f;
    for (int layer = 0; layer < NLAYERS; layer++) {
        const float* la = g_logabs + layer * NBATCH;
        float mx = -1e30f;
        for (int b = tid; b < NBATCH; b += 1024) {
            float v = __half2float(__float2half(la[b]));
            mx = fmaxf(mx, v);
        }
        red[tid] = mx; __syncthreads();
        for (int s2 = 512; s2; s2 >>= 1) {
            if (tid < s2) red[tid] = fmaxf(red[tid], red[tid + s2]);
            __syncthreads();
        }
        float gmx = red[0]; __syncthreads();
        __half maxh = __float2half(gmx);
        float sum = 0.f;
        for (int b = tid; b < NBATCH; b += 1024) {
            __half xh = __float2half(la[b]);
            __half d = __hsub(xh, maxh);
            float e = expf(__half2float(d));
            sum += __half2float(__float2half(e));
        }
        red[tid] = sum; __syncthreads();
        for (int s2 = 512; s2; s2 >>= 1) {
            if (tid < s2) red[tid] += red[tid + s2];
            __syncthreads();
        }
        float tot = red[0]; __syncthreads();
        __half resh = __hadd(maxh, __float2half(logf(tot)));
        ldj += __half2float(resh);
    }
    if (tid == 0) out[(size_t)NBATCH * LAT] = ldj;
}

// ---------------------------------------------------------------------------
extern "C" void kernel_launch(void* const* d_in, const int* in_sizes, int n_in,
                              void* d_out, int out_size)
{
    const float* z  = (const float*)d_in[0];
    const float* W1 = (const float*)d_in[1];
    const float* b1 = (const float*)d_in[2];
    const float* W2 = (const float*)d_in[3];
    const float* b2 = (const float*)d_in[4];
    float* out = (float*)d_out;

    const size_t SM0 = (size_t)(64 * 257) * sizeof(float);
    const size_t SM1 = (size_t)(64 * 260 + 256 * 68 + 64 * 260 + 64 * 68 + 256 + 64) * sizeof(float);
    const size_t SMB = (size_t)(HID * LAT * 2 + LAT * LAT) * sizeof(float)
                     + (size_t)(GB * 256) * sizeof(unsigned short)
                     + (size_t)(3 * GB + 32) * sizeof(float);

    cudaFuncSetAttribute(precomp_kernel, cudaFuncAttributeMaxDynamicSharedMemorySize, (int)SM0);
    cudaFuncSetAttribute(fwd_kernel, cudaFuncAttributeMaxDynamicSharedMemorySize, (int)SM1);
    cudaFuncSetAttribute(build_kernel, cudaFuncAttributeMaxDynamicSharedMemorySize, (int)SMB);

    precomp_kernel<<<NLAYERS, 256, SM0>>>(W1, W2);
    fwd_kernel<<<NBATCH / TB, 256, SM1>>>(z, W1, b1, W2, b2, out);
    dim3 gb(NBATCH / GB, NLAYERS);
    build_kernel<<<gb, 512, SMB>>>(W1);
    lu_kernel<<<(NITEMS + LUW - 1) / LUW, LUW * 32>>>();
    reduce_kernel<<<1, 1024>>>(out);
}